// round 11
// baseline (speedup 1.0000x reference)
#include <cuda_runtime.h>
#include <cuda_bf16.h>
#include <cstdint>

#define MM 9
#define DD 128
#define NMAX 8192

// ---------------- global scratch (static, no dynamic alloc) ----------------
static __device__ __align__(128) float g_g[NMAX * MM * DD];

// ---------------- helpers ---------------------------------------------------
__device__ __forceinline__ uint32_t bswz(int row, int q) {
    int c = q >> 1;
    int cs = (c & 8) | ((c & 7) ^ (row & 7));
    return (uint32_t)(row * 256 + cs * 16 + (q & 1) * 8);
}
__device__ __forceinline__ uint32_t lmaddr(uint32_t base, int row, int chunk) {
    int cs = (chunk & 8) | ((chunk & 7) ^ (row & 7));
    return base + (uint32_t)(row * 256 + cs * 16);
}
__device__ __forceinline__ uint32_t smem_u32(const void* p) {
    uint32_t a;
    asm("{ .reg .u64 t; cvta.to.shared.u64 t, %1; cvt.u32.u64 %0, t; }" : "=r"(a) : "l"(p));
    return a;
}
#define LDSM_X4(r0, r1, r2, r3, a) \
    asm volatile("ldmatrix.sync.aligned.m8n8.x4.shared.b16 {%0,%1,%2,%3}, [%4];" \
                 : "=r"(r0), "=r"(r1), "=r"(r2), "=r"(r3) : "r"(a))
#define HMMA(d0, d1, d2, d3, a0, a1, a2, a3, b0, b1) \
    asm volatile("mma.sync.aligned.m16n8k16.row.col.f32.bf16.bf16.f32 " \
                 "{%0,%1,%2,%3}, {%4,%5,%6,%7}, {%8,%9}, {%0,%1,%2,%3};" \
                 : "+f"(d0), "+f"(d1), "+f"(d2), "+f"(d3) \
                 : "r"(a0), "r"(a1), "r"(a2), "r"(a3), "r"(b0), "r"(b1))

__device__ __forceinline__ void st_split_g(char* hi, char* lo, uint32_t a, float4 v) {
    __nv_bfloat16 hx = __float2bfloat16(v.x), hy = __float2bfloat16(v.y);
    __nv_bfloat16 hz = __float2bfloat16(v.z), hw = __float2bfloat16(v.w);
    __nv_bfloat16 lx = __float2bfloat16(v.x - __bfloat162float(hx));
    __nv_bfloat16 ly = __float2bfloat16(v.y - __bfloat162float(hy));
    __nv_bfloat16 lz = __float2bfloat16(v.z - __bfloat162float(hz));
    __nv_bfloat16 lw = __float2bfloat16(v.w - __bfloat162float(hw));
    uint2 h = make_uint2((uint32_t)__bfloat16_as_ushort(hx) | ((uint32_t)__bfloat16_as_ushort(hy) << 16),
                         (uint32_t)__bfloat16_as_ushort(hz) | ((uint32_t)__bfloat16_as_ushort(hw) << 16));
    uint2 l = make_uint2((uint32_t)__bfloat16_as_ushort(lx) | ((uint32_t)__bfloat16_as_ushort(ly) << 16),
                         (uint32_t)__bfloat16_as_ushort(lz) | ((uint32_t)__bfloat16_as_ushort(lw) << 16));
    *reinterpret_cast<uint2*>(hi + a) = h;
    *reinterpret_cast<uint2*>(lo + a) = l;
}

// ---------------- K1: persistent-W split-bf16 HMMA, r=2 c=4 warp split -------
// grid (32, 9), 256 thr; smem: fhi 16K | flo 16K | Whi 32K | Wlo 32K = 96K
#define SM_FHI 0
#define SM_FLO 16384
#define SM_WHI 32768
#define SM_WLO 65536
#define K1_SMEM 98304
#define NTILE_STRIDE 32

__global__ void __launch_bounds__(256, 2)
k1_gemm(const float* __restrict__ F, const float* __restrict__ Wg, int N)
{
    extern __shared__ char smem[];
    const uint32_t sb = smem_u32(smem);
    const int tid  = threadIdx.x;
    const int lane = tid & 31;
    const int warp = tid >> 5;          // 0..7
    const int rg   = warp & 1;          // rows [32rg, 32rg+32)
    const int cg   = warp >> 1;         // cols [32cg, 32cg+32)
    const int m    = blockIdx.y;
    const int ntiles = (N + 63) / 64;
    const float4* Fg4 = reinterpret_cast<const float4*>(F);
    const float4* Wg4 = reinterpret_cast<const float4*>(Wg);

    // loader geometry: 8 float4 slots per thread
    int lrow[8], lq[8];
    #pragma unroll
    for (int it = 0; it < 8; ++it) {
        int s = tid + it * 256;          // 0..2047
        lrow[it] = s >> 5; lq[it] = s & 31;
    }

    // prefetch f for first tile (long-latency LDGs issued first)
    float4 fraw[8];
    {
        const int n0 = blockIdx.x * 64;
        #pragma unroll
        for (int it = 0; it < 8; ++it) {
            int n = n0 + lrow[it];
            fraw[it] = make_float4(0.f, 0.f, 0.f, 0.f);
            if (n < N) fraw[it] = Fg4[((size_t)n * MM + m) * 32 + lq[it]];
        }
    }

    // convert W_m (fp32, L2-resident) into split-bf16 smem, ONCE per CTA
    #pragma unroll
    for (int it = 0; it < 16; ++it) {
        int s = tid + it * 256;            // 0..4095
        int row = s >> 5, q = s & 31;
        st_split_g(smem + SM_WHI, smem + SM_WLO, bswz(row, q),
                   Wg4[(size_t)m * 4096 + s]);
    }
    __syncthreads();           // W resident

    const int a_row0 = 32 * rg + (lane & 15);           // rowtile 0; +16 for rt1
    const int a_ch   = lane >> 4;
    const int b_rlo  = (lane & 7) + ((lane >> 4) << 3);
    const int b_ch   = (lane >> 3) & 1;

    for (int t = blockIdx.x; t < ntiles; t += NTILE_STRIDE) {
        const int n0 = t * 64;

        // convert current f tile into split smem
        #pragma unroll
        for (int it = 0; it < 8; ++it)
            st_split_g(smem + SM_FHI, smem + SM_FLO, bswz(lrow[it], lq[it]), fraw[it]);
        __syncthreads();

        // prefetch next tile's raw f (overlaps the MMA chain below)
        const int tn = t + NTILE_STRIDE;
        if (tn < ntiles) {
            const int nn0 = tn * 64;
            #pragma unroll
            for (int it = 0; it < 8; ++it) {
                int n = nn0 + lrow[it];
                fraw[it] = make_float4(0.f, 0.f, 0.f, 0.f);
                if (n < N) fraw[it] = Fg4[((size_t)n * MM + m) * 32 + lq[it]];
            }
        }

        // acc[rt][q][c]: rowtile rt (16 rows), n8-tile q (cols 32cg + 8q)
        float acc[2][4][4];
        #pragma unroll
        for (int rt = 0; rt < 2; ++rt)
            #pragma unroll
            for (int q = 0; q < 4; ++q)
                #pragma unroll
                for (int c = 0; c < 4; ++c) acc[rt][q][c] = 0.f;

        #pragma unroll
        for (int kk = 0; kk < 8; ++kk) {
            uint32_t ah[2][4], al[2][4];
            #pragma unroll
            for (int rt = 0; rt < 2; ++rt) {
                LDSM_X4(ah[rt][0], ah[rt][1], ah[rt][2], ah[rt][3],
                        lmaddr(sb + SM_FHI, a_row0 + 16 * rt, 2 * kk + a_ch));
                LDSM_X4(al[rt][0], al[rt][1], al[rt][2], al[rt][3],
                        lmaddr(sb + SM_FLO, a_row0 + 16 * rt, 2 * kk + a_ch));
            }
            uint32_t bh[2][4], bl[2][4];
            #pragma unroll
            for (int ct = 0; ct < 2; ++ct) {
                const int brow = 32 * cg + 16 * ct + b_rlo;
                LDSM_X4(bh[ct][0], bh[ct][1], bh[ct][2], bh[ct][3],
                        lmaddr(sb + SM_WHI, brow, 2 * kk + b_ch));
                LDSM_X4(bl[ct][0], bl[ct][1], bl[ct][2], bl[ct][3],
                        lmaddr(sb + SM_WLO, brow, 2 * kk + b_ch));
            }
            #pragma unroll
            for (int rt = 0; rt < 2; ++rt) {
                #pragma unroll
                for (int q = 0; q < 4; ++q) {
                    const int ct = q >> 1, h = (q & 1) * 2;
                    HMMA(acc[rt][q][0], acc[rt][q][1], acc[rt][q][2], acc[rt][q][3],
                         ah[rt][0], ah[rt][1], ah[rt][2], ah[rt][3],
                         bh[ct][h], bh[ct][h + 1]);
                    HMMA(acc[rt][q][0], acc[rt][q][1], acc[rt][q][2], acc[rt][q][3],
                         ah[rt][0], ah[rt][1], ah[rt][2], ah[rt][3],
                         bl[ct][h], bl[ct][h + 1]);
                    HMMA(acc[rt][q][0], acc[rt][q][1], acc[rt][q][2], acc[rt][q][3],
                         al[rt][0], al[rt][1], al[rt][2], al[rt][3],
                         bh[ct][h], bh[ct][h + 1]);
                }
            }
        }

        // relu + store g[n][m][col]
        #pragma unroll
        for (int rt = 0; rt < 2; ++rt) {
            const int r0 = n0 + 32 * rg + 16 * rt + (lane >> 2);
            const int cb = 32 * cg + (lane & 3) * 2;
            #pragma unroll
            for (int q = 0; q < 4; ++q) {
                const int col = cb + 8 * q;
                if (r0 < N) {
                    float2 v = make_float2(fmaxf(acc[rt][q][0], 0.f), fmaxf(acc[rt][q][1], 0.f));
                    *reinterpret_cast<float2*>(g_g + ((size_t)r0 * MM + m) * DD + col) = v;
                }
                if (r0 + 8 < N) {
                    float2 v = make_float2(fmaxf(acc[rt][q][2], 0.f), fmaxf(acc[rt][q][3], 0.f));
                    *reinterpret_cast<float2*>(g_g + ((size_t)(r0 + 8) * MM + m) * DD + col) = v;
                }
            }
        }
        __syncthreads();   // f smem consumed; safe to overwrite next iteration
    }
}

// ---------------- K2: 16-lane phase 2 with saturated tanh --------------------
// warp = 2 examples; lane sl = lane&15 owns dims [8sl, 8sl+8)
__global__ void __launch_bounds__(256)
k2_phase2(const float* __restrict__ F, float* __restrict__ out, int N)
{
    const int lane = threadIdx.x & 31;
    const int warp = threadIdx.x >> 5;
    const int ex   = lane >> 4;          // 0..1
    const int sl   = lane & 15;          // 0..15
    const int nr   = blockIdx.x * 16 + warp * 2 + ex;
    const int n    = (nr < N) ? nr : (N - 1);   // clamp: keep warp converged
    const float4* g4  = reinterpret_cast<const float4*>(g_g);
    const float4* Fg4 = reinterpret_cast<const float4*>(F);
    float4* out4 = reinterpret_cast<float4*>(out);

    // load g: 9 slots x 8 dims (2 float4 each)
    float4 gm[MM][2];
    #pragma unroll
    for (int m = 0; m < MM; ++m) {
        gm[m][0] = g4[((size_t)n * MM + m) * 32 + sl * 2 + 0];
        gm[m][1] = g4[((size_t)n * MM + m) * 32 + sl * 2 + 1];
    }
    // fsum over m (exact fp32)
    float4 fs0 = Fg4[((size_t)n * MM) * 32 + sl * 2 + 0];
    float4 fs1 = Fg4[((size_t)n * MM) * 32 + sl * 2 + 1];
    #pragma unroll
    for (int m = 1; m < MM; ++m) {
        float4 v0 = Fg4[((size_t)n * MM + m) * 32 + sl * 2 + 0];
        float4 v1 = Fg4[((size_t)n * MM + m) * 32 + sl * 2 + 1];
        fs0.x += v0.x; fs0.y += v0.y; fs0.z += v0.z; fs0.w += v0.w;
        fs1.x += v1.x; fs1.y += v1.y; fs1.z += v1.z; fs1.w += v1.w;
    }

    // pairwise distances: 4-step butterfly within 16-lane group.
    // edge: fp32 tanh(sqrt(s)) saturates to exactly 1.0f for s > 85
    // (1 - tanh < 2^-25); fallback path is the exact computation.
    float cs[MM];
    #pragma unroll
    for (int k = 0; k < MM; ++k) cs[k] = 0.f;

    #pragma unroll
    for (int j = 0; j < MM; ++j) {
        #pragma unroll
        for (int k = j + 1; k < MM; ++k) {
            float dx = gm[j][0].x - gm[k][0].x;
            float dy = gm[j][0].y - gm[k][0].y;
            float dz = gm[j][0].z - gm[k][0].z;
            float dw = gm[j][0].w - gm[k][0].w;
            float s = dx * dx;
            s = fmaf(dy, dy, s);
            s = fmaf(dz, dz, s);
            s = fmaf(dw, dw, s);
            dx = gm[j][1].x - gm[k][1].x;
            dy = gm[j][1].y - gm[k][1].y;
            dz = gm[j][1].z - gm[k][1].z;
            dw = gm[j][1].w - gm[k][1].w;
            s = fmaf(dx, dx, s);
            s = fmaf(dy, dy, s);
            s = fmaf(dz, dz, s);
            s = fmaf(dw, dw, s);
            s += __shfl_xor_sync(0xffffffffu, s, 8);
            s += __shfl_xor_sync(0xffffffffu, s, 4);
            s += __shfl_xor_sync(0xffffffffu, s, 2);
            s += __shfl_xor_sync(0xffffffffu, s, 1);
            float e;
            if (s > 85.f) {
                e = 1.f;
            } else {
                float x = (s > 0.f) ? s * __frsqrt_rn(s) : 0.f;
                e = 1.f - __fdividef(2.f, __expf(2.f * x) + 1.f);
            }
            cs[j] += e;
            cs[k] += e;
        }
    }

    // updates: u = sum_k cs[k] * g[k]
    float4 u0 = make_float4(0.f, 0.f, 0.f, 0.f);
    float4 u1 = make_float4(0.f, 0.f, 0.f, 0.f);
    #pragma unroll
    for (int k = 0; k < MM; ++k) {
        u0.x = fmaf(cs[k], gm[k][0].x, u0.x);
        u0.y = fmaf(cs[k], gm[k][0].y, u0.y);
        u0.z = fmaf(cs[k], gm[k][0].z, u0.z);
        u0.w = fmaf(cs[k], gm[k][0].w, u0.w);
        u1.x = fmaf(cs[k], gm[k][1].x, u1.x);
        u1.y = fmaf(cs[k], gm[k][1].y, u1.y);
        u1.z = fmaf(cs[k], gm[k][1].z, u1.z);
        u1.w = fmaf(cs[k], gm[k][1].w, u1.w);
    }

    if (nr < N) {
        float4 o0, o1;
        o0.x = 0.5f * (fs0.x + u0.x);
        o0.y = 0.5f * (fs0.y + u0.y);
        o0.z = 0.5f * (fs0.z + u0.z);
        o0.w = 0.5f * (fs0.w + u0.w);
        o1.x = 0.5f * (fs1.x + u1.x);
        o1.y = 0.5f * (fs1.y + u1.y);
        o1.z = 0.5f * (fs1.z + u1.z);
        o1.w = 0.5f * (fs1.w + u1.w);
        out4[(size_t)nr * 32 + sl * 2 + 0] = o0;
        out4[(size_t)nr * 32 + sl * 2 + 1] = o1;
    }
}

// ----------------------------------------------------------------------------
extern "C" void kernel_launch(void* const* d_in, const int* in_sizes, int n_in,
                              void* d_out, int out_size) {
    const float* F = (const float*)d_in[0];   // [N,9,128] fp32
    const float* W = (const float*)d_in[1];   // [9,128,128] fp32
    float* out = (float*)d_out;               // [N,128] fp32
    const int N = in_sizes[0] / (MM * DD);

    cudaFuncSetAttribute(k1_gemm, cudaFuncAttributeMaxDynamicSharedMemorySize, K1_SMEM);

    dim3 g1(NTILE_STRIDE, MM);
    k1_gemm<<<g1, 256, K1_SMEM>>>(F, W, N);
    k2_phase2<<<(N + 15) / 16, 256>>>(F, out, N);
}

// round 12
// speedup vs baseline: 1.0911x; 1.0911x over previous
#include <cuda_runtime.h>
#include <cuda_bf16.h>
#include <cuda_fp16.h>
#include <cstdint>

#define MM 9
#define DD 128
#define NMAX 8192

// ---------------- global scratch (static, no dynamic alloc) ----------------
static __device__ __align__(128) __half g_h[NMAX * MM * DD];   // 18.9 MB fp16

// ---------------- helpers ---------------------------------------------------
__device__ __forceinline__ uint32_t bswz(int row, int q) {
    int c = q >> 1;
    int cs = (c & 8) | ((c & 7) ^ (row & 7));
    return (uint32_t)(row * 256 + cs * 16 + (q & 1) * 8);
}
__device__ __forceinline__ uint32_t lmaddr(uint32_t base, int row, int chunk) {
    int cs = (chunk & 8) | ((chunk & 7) ^ (row & 7));
    return base + (uint32_t)(row * 256 + cs * 16);
}
__device__ __forceinline__ uint32_t smem_u32(const void* p) {
    uint32_t a;
    asm("{ .reg .u64 t; cvta.to.shared.u64 t, %1; cvt.u32.u64 %0, t; }" : "=r"(a) : "l"(p));
    return a;
}
#define LDSM_X4(r0, r1, r2, r3, a) \
    asm volatile("ldmatrix.sync.aligned.m8n8.x4.shared.b16 {%0,%1,%2,%3}, [%4];" \
                 : "=r"(r0), "=r"(r1), "=r"(r2), "=r"(r3) : "r"(a))
#define HMMA(d0, d1, d2, d3, a0, a1, a2, a3, b0, b1) \
    asm volatile("mma.sync.aligned.m16n8k16.row.col.f32.bf16.bf16.f32 " \
                 "{%0,%1,%2,%3}, {%4,%5,%6,%7}, {%8,%9}, {%0,%1,%2,%3};" \
                 : "+f"(d0), "+f"(d1), "+f"(d2), "+f"(d3) \
                 : "r"(a0), "r"(a1), "r"(a2), "r"(a3), "r"(b0), "r"(b1))

__device__ __forceinline__ void st_split_g(char* hi, char* lo, uint32_t a, float4 v) {
    __nv_bfloat16 hx = __float2bfloat16(v.x), hy = __float2bfloat16(v.y);
    __nv_bfloat16 hz = __float2bfloat16(v.z), hw = __float2bfloat16(v.w);
    __nv_bfloat16 lx = __float2bfloat16(v.x - __bfloat162float(hx));
    __nv_bfloat16 ly = __float2bfloat16(v.y - __bfloat162float(hy));
    __nv_bfloat16 lz = __float2bfloat16(v.z - __bfloat162float(hz));
    __nv_bfloat16 lw = __float2bfloat16(v.w - __bfloat162float(hw));
    uint2 h = make_uint2((uint32_t)__bfloat16_as_ushort(hx) | ((uint32_t)__bfloat16_as_ushort(hy) << 16),
                         (uint32_t)__bfloat16_as_ushort(hz) | ((uint32_t)__bfloat16_as_ushort(hw) << 16));
    uint2 l = make_uint2((uint32_t)__bfloat16_as_ushort(lx) | ((uint32_t)__bfloat16_as_ushort(ly) << 16),
                         (uint32_t)__bfloat16_as_ushort(lz) | ((uint32_t)__bfloat16_as_ushort(lw) << 16));
    *reinterpret_cast<uint2*>(hi + a) = h;
    *reinterpret_cast<uint2*>(lo + a) = l;
}

__device__ __forceinline__ constexpr int pidx(int j, int k) {
    return j * 8 - j * (j - 1) / 2 + (k - j - 1);
}

// ---------------- K1: persistent-W split-bf16 HMMA, r=2 c=4, fp16 g out ------
// grid (32, 9), 256 thr; smem: fhi 16K | flo 16K | Whi 32K | Wlo 32K = 96K
#define SM_FHI 0
#define SM_FLO 16384
#define SM_WHI 32768
#define SM_WLO 65536
#define K1_SMEM 98304
#define NTILE_STRIDE 32

__global__ void __launch_bounds__(256, 2)
k1_gemm(const float* __restrict__ F, const float* __restrict__ Wg, int N)
{
    extern __shared__ char smem[];
    const uint32_t sb = smem_u32(smem);
    const int tid  = threadIdx.x;
    const int lane = tid & 31;
    const int warp = tid >> 5;          // 0..7
    const int rg   = warp & 1;          // rows [32rg, 32rg+32)
    const int cg   = warp >> 1;         // cols [32cg, 32cg+32)
    const int m    = blockIdx.y;
    const int ntiles = (N + 63) / 64;
    const float4* Fg4 = reinterpret_cast<const float4*>(F);
    const float4* Wg4 = reinterpret_cast<const float4*>(Wg);

    // loader geometry: 8 float4 slots per thread
    int lrow[8], lq[8];
    #pragma unroll
    for (int it = 0; it < 8; ++it) {
        int s = tid + it * 256;          // 0..2047
        lrow[it] = s >> 5; lq[it] = s & 31;
    }

    // prefetch f for first tile (long-latency LDGs issued first)
    float4 fraw[8];
    {
        const int n0 = blockIdx.x * 64;
        #pragma unroll
        for (int it = 0; it < 8; ++it) {
            int n = n0 + lrow[it];
            fraw[it] = make_float4(0.f, 0.f, 0.f, 0.f);
            if (n < N) fraw[it] = Fg4[((size_t)n * MM + m) * 32 + lq[it]];
        }
    }

    // convert W_m (fp32, L2-resident) into split-bf16 smem, ONCE per CTA
    #pragma unroll
    for (int it = 0; it < 16; ++it) {
        int s = tid + it * 256;            // 0..4095
        int row = s >> 5, q = s & 31;
        st_split_g(smem + SM_WHI, smem + SM_WLO, bswz(row, q),
                   Wg4[(size_t)m * 4096 + s]);
    }
    __syncthreads();           // W resident

    const int a_row0 = 32 * rg + (lane & 15);           // rowtile 0; +16 for rt1
    const int a_ch   = lane >> 4;
    const int b_rlo  = (lane & 7) + ((lane >> 4) << 3);
    const int b_ch   = (lane >> 3) & 1;

    for (int t = blockIdx.x; t < ntiles; t += NTILE_STRIDE) {
        const int n0 = t * 64;

        // convert current f tile into split smem
        #pragma unroll
        for (int it = 0; it < 8; ++it)
            st_split_g(smem + SM_FHI, smem + SM_FLO, bswz(lrow[it], lq[it]), fraw[it]);
        __syncthreads();

        // prefetch next tile's raw f (overlaps the MMA chain below)
        const int tn = t + NTILE_STRIDE;
        if (tn < ntiles) {
            const int nn0 = tn * 64;
            #pragma unroll
            for (int it = 0; it < 8; ++it) {
                int n = nn0 + lrow[it];
                fraw[it] = make_float4(0.f, 0.f, 0.f, 0.f);
                if (n < N) fraw[it] = Fg4[((size_t)n * MM + m) * 32 + lq[it]];
            }
        }

        // acc[rt][q][c]: rowtile rt (16 rows), n8-tile q (cols 32cg + 8q)
        float acc[2][4][4];
        #pragma unroll
        for (int rt = 0; rt < 2; ++rt)
            #pragma unroll
            for (int q = 0; q < 4; ++q)
                #pragma unroll
                for (int c = 0; c < 4; ++c) acc[rt][q][c] = 0.f;

        #pragma unroll
        for (int kk = 0; kk < 8; ++kk) {
            uint32_t ah[2][4], al[2][4];
            #pragma unroll
            for (int rt = 0; rt < 2; ++rt) {
                LDSM_X4(ah[rt][0], ah[rt][1], ah[rt][2], ah[rt][3],
                        lmaddr(sb + SM_FHI, a_row0 + 16 * rt, 2 * kk + a_ch));
                LDSM_X4(al[rt][0], al[rt][1], al[rt][2], al[rt][3],
                        lmaddr(sb + SM_FLO, a_row0 + 16 * rt, 2 * kk + a_ch));
            }
            uint32_t bh[2][4], bl[2][4];
            #pragma unroll
            for (int ct = 0; ct < 2; ++ct) {
                const int brow = 32 * cg + 16 * ct + b_rlo;
                LDSM_X4(bh[ct][0], bh[ct][1], bh[ct][2], bh[ct][3],
                        lmaddr(sb + SM_WHI, brow, 2 * kk + b_ch));
                LDSM_X4(bl[ct][0], bl[ct][1], bl[ct][2], bl[ct][3],
                        lmaddr(sb + SM_WLO, brow, 2 * kk + b_ch));
            }
            #pragma unroll
            for (int rt = 0; rt < 2; ++rt) {
                #pragma unroll
                for (int q = 0; q < 4; ++q) {
                    const int ct = q >> 1, h = (q & 1) * 2;
                    HMMA(acc[rt][q][0], acc[rt][q][1], acc[rt][q][2], acc[rt][q][3],
                         ah[rt][0], ah[rt][1], ah[rt][2], ah[rt][3],
                         bh[ct][h], bh[ct][h + 1]);
                    HMMA(acc[rt][q][0], acc[rt][q][1], acc[rt][q][2], acc[rt][q][3],
                         ah[rt][0], ah[rt][1], ah[rt][2], ah[rt][3],
                         bl[ct][h], bl[ct][h + 1]);
                    HMMA(acc[rt][q][0], acc[rt][q][1], acc[rt][q][2], acc[rt][q][3],
                         al[rt][0], al[rt][1], al[rt][2], al[rt][3],
                         bh[ct][h], bh[ct][h + 1]);
                }
            }
        }

        // relu + store g as fp16
        #pragma unroll
        for (int rt = 0; rt < 2; ++rt) {
            const int r0 = n0 + 32 * rg + 16 * rt + (lane >> 2);
            const int cb = 32 * cg + (lane & 3) * 2;
            #pragma unroll
            for (int q = 0; q < 4; ++q) {
                const int col = cb + 8 * q;
                if (r0 < N) {
                    __half2 v = __floats2half2_rn(fmaxf(acc[rt][q][0], 0.f),
                                                  fmaxf(acc[rt][q][1], 0.f));
                    *reinterpret_cast<__half2*>(g_h + ((size_t)r0 * MM + m) * DD + col) = v;
                }
                if (r0 + 8 < N) {
                    __half2 v = __floats2half2_rn(fmaxf(acc[rt][q][2], 0.f),
                                                  fmaxf(acc[rt][q][3], 0.f));
                    *reinterpret_cast<__half2*>(g_h + ((size_t)(r0 + 8) * MM + m) * DD + col) = v;
                }
            }
        }
        __syncthreads();   // f smem consumed; safe to overwrite next iteration
    }
}

// ---------------- K2: R8-validated 32-lane phase 2, fp16 g in ----------------
__global__ void __launch_bounds__(256)
k2_phase2(const float* __restrict__ F, float* __restrict__ out, int N)
{
    const int lane = threadIdx.x & 31;
    const int warp = threadIdx.x >> 5;
    const int n0   = blockIdx.x * 16;
    const float4* Fg4 = reinterpret_cast<const float4*>(F);
    float4* out4 = reinterpret_cast<float4*>(out);

    #pragma unroll
    for (int ii = 0; ii < 2; ++ii) {
        const int n = n0 + warp * 2 + ii;
        if (n >= N) continue;

        // g: lane owns dims [4*lane, 4*lane+4), fp16 -> fp32
        float4 gm[MM];
        #pragma unroll
        for (int m = 0; m < MM; ++m) {
            uint2 raw = *reinterpret_cast<const uint2*>(
                g_h + ((size_t)n * MM + m) * DD + lane * 4);
            float2 f0 = __half22float2(*reinterpret_cast<const __half2*>(&raw.x));
            float2 f1 = __half22float2(*reinterpret_cast<const __half2*>(&raw.y));
            gm[m] = make_float4(f0.x, f0.y, f1.x, f1.y);
        }

        // fsum over m (exact fp32)
        float4 fs = Fg4[((size_t)n * MM) * 32 + lane];
        #pragma unroll
        for (int m = 1; m < MM; ++m) {
            float4 v = Fg4[((size_t)n * MM + m) * 32 + lane];
            fs.x += v.x; fs.y += v.y; fs.z += v.z; fs.w += v.w;
        }

        float mysA = 1.f, mysB = 1.f;
        #pragma unroll
        for (int j = 0; j < MM; ++j) {
            #pragma unroll
            for (int k = j + 1; k < MM; ++k) {
                const int p = pidx(j, k);
                float dx = gm[j].x - gm[k].x;
                float dy = gm[j].y - gm[k].y;
                float dz = gm[j].z - gm[k].z;
                float dw = gm[j].w - gm[k].w;
                float s = dx * dx;
                s = fmaf(dy, dy, s);
                s = fmaf(dz, dz, s);
                s = fmaf(dw, dw, s);
                s += __shfl_xor_sync(0xffffffffu, s, 16);
                s += __shfl_xor_sync(0xffffffffu, s, 8);
                s += __shfl_xor_sync(0xffffffffu, s, 4);
                s += __shfl_xor_sync(0xffffffffu, s, 2);
                s += __shfl_xor_sync(0xffffffffu, s, 1);
                if (p < 32) { if (lane == p)      mysA = s; }
                else        { if (lane == p - 32) mysB = s; }
            }
        }

        float xA = (mysA > 0.f) ? mysA * __frsqrt_rn(mysA) : 0.f;
        float xB = (mysB > 0.f) ? mysB * __frsqrt_rn(mysB) : 0.f;
        float eA = 1.f - __fdividef(2.f, __expf(2.f * xA) + 1.f);
        float eB = 1.f - __fdividef(2.f, __expf(2.f * xB) + 1.f);

        float cs[MM];
        #pragma unroll
        for (int k = 0; k < MM; ++k) {
            float a = 0.f;
            #pragma unroll
            for (int j = 0; j < MM; ++j) {
                if (j == k) continue;
                const int p = (j < k) ? pidx(j, k) : pidx(k, j);
                float e = (p < 32) ? __shfl_sync(0xffffffffu, eA, p)
                                   : __shfl_sync(0xffffffffu, eB, p - 32);
                a += e;
            }
            cs[k] = a;
        }

        float ux = 0.f, uy = 0.f, uz = 0.f, uw = 0.f;
        #pragma unroll
        for (int k = 0; k < MM; ++k) {
            ux = fmaf(cs[k], gm[k].x, ux);
            uy = fmaf(cs[k], gm[k].y, uy);
            uz = fmaf(cs[k], gm[k].z, uz);
            uw = fmaf(cs[k], gm[k].w, uw);
        }
        float4 o;
        o.x = 0.5f * (fs.x + ux);
        o.y = 0.5f * (fs.y + uy);
        o.z = 0.5f * (fs.z + uz);
        o.w = 0.5f * (fs.w + uw);
        out4[(size_t)n * 32 + lane] = o;
    }
}

// ----------------------------------------------------------------------------
extern "C" void kernel_launch(void* const* d_in, const int* in_sizes, int n_in,
                              void* d_out, int out_size) {
    const float* F = (const float*)d_in[0];   // [N,9,128] fp32
    const float* W = (const float*)d_in[1];   // [9,128,128] fp32
    float* out = (float*)d_out;               // [N,128] fp32
    const int N = in_sizes[0] / (MM * DD);

    cudaFuncSetAttribute(k1_gemm, cudaFuncAttributeMaxDynamicSharedMemorySize, K1_SMEM);

    dim3 g1(NTILE_STRIDE, MM);
    k1_gemm<<<g1, 256, K1_SMEM>>>(F, W, N);
    k2_phase2<<<(N + 15) / 16, 256>>>(F, out, N);
}

// round 14
// speedup vs baseline: 1.3091x; 1.1998x over previous
#include <cuda_runtime.h>
#include <cuda_bf16.h>
#include <cuda_fp16.h>
#include <cstdint>

#define MM 9
#define DD 128
#define NMAX 8192

// ---------------- global scratch (static, no dynamic alloc) ----------------
static __device__ __align__(128) __half g_h[NMAX * MM * DD];   // 18.9 MB fp16

// pair index tables: pair p -> (j, k), j < k
static __device__ const int PJ_d[36] =
    {0,0,0,0,0,0,0,0, 1,1,1,1,1,1,1, 2,2,2,2,2,2, 3,3,3,3,3, 4,4,4,4, 5,5,5, 6,6, 7};
static __device__ const int PK_d[36] =
    {1,2,3,4,5,6,7,8, 2,3,4,5,6,7,8, 3,4,5,6,7,8, 4,5,6,7,8, 5,6,7,8, 6,7,8, 7,8, 8};

// ---------------- helpers ---------------------------------------------------
__device__ __forceinline__ uint32_t bswz(int row, int q) {
    int c = q >> 1;
    int cs = (c & 8) | ((c & 7) ^ (row & 7));
    return (uint32_t)(row * 256 + cs * 16 + (q & 1) * 8);
}
__device__ __forceinline__ uint32_t lmaddr(uint32_t base, int row, int chunk) {
    int cs = (chunk & 8) | ((chunk & 7) ^ (row & 7));
    return base + (uint32_t)(row * 256 + cs * 16);
}
__device__ __forceinline__ uint32_t smem_u32(const void* p) {
    uint32_t a;
    asm("{ .reg .u64 t; cvta.to.shared.u64 t, %1; cvt.u32.u64 %0, t; }" : "=r"(a) : "l"(p));
    return a;
}
#define LDSM_X4(r0, r1, r2, r3, a) \
    asm volatile("ldmatrix.sync.aligned.m8n8.x4.shared.b16 {%0,%1,%2,%3}, [%4];" \
                 : "=r"(r0), "=r"(r1), "=r"(r2), "=r"(r3) : "r"(a))
#define HMMA(d0, d1, d2, d3, a0, a1, a2, a3, b0, b1) \
    asm volatile("mma.sync.aligned.m16n8k16.row.col.f32.bf16.bf16.f32 " \
                 "{%0,%1,%2,%3}, {%4,%5,%6,%7}, {%8,%9}, {%0,%1,%2,%3};" \
                 : "+f"(d0), "+f"(d1), "+f"(d2), "+f"(d3) \
                 : "r"(a0), "r"(a1), "r"(a2), "r"(a3), "r"(b0), "r"(b1))
#define HMMA16(d0, d1, d2, d3, a0, a1, a2, a3, b0, b1) \
    asm volatile("mma.sync.aligned.m16n8k16.row.col.f32.f16.f16.f32 " \
                 "{%0,%1,%2,%3}, {%4,%5,%6,%7}, {%8,%9}, {%0,%1,%2,%3};" \
                 : "+f"(d0), "+f"(d1), "+f"(d2), "+f"(d3) \
                 : "r"(a0), "r"(a1), "r"(a2), "r"(a3), "r"(b0), "r"(b1))

__device__ __forceinline__ void st_split_g(char* hi, char* lo, uint32_t a, float4 v) {
    __nv_bfloat16 hx = __float2bfloat16(v.x), hy = __float2bfloat16(v.y);
    __nv_bfloat16 hz = __float2bfloat16(v.z), hw = __float2bfloat16(v.w);
    __nv_bfloat16 lx = __float2bfloat16(v.x - __bfloat162float(hx));
    __nv_bfloat16 ly = __float2bfloat16(v.y - __bfloat162float(hy));
    __nv_bfloat16 lz = __float2bfloat16(v.z - __bfloat162float(hz));
    __nv_bfloat16 lw = __float2bfloat16(v.w - __bfloat162float(hw));
    uint2 h = make_uint2((uint32_t)__bfloat16_as_ushort(hx) | ((uint32_t)__bfloat16_as_ushort(hy) << 16),
                         (uint32_t)__bfloat16_as_ushort(hz) | ((uint32_t)__bfloat16_as_ushort(hw) << 16));
    uint2 l = make_uint2((uint32_t)__bfloat16_as_ushort(lx) | ((uint32_t)__bfloat16_as_ushort(ly) << 16),
                         (uint32_t)__bfloat16_as_ushort(lz) | ((uint32_t)__bfloat16_as_ushort(lw) << 16));
    *reinterpret_cast<uint2*>(hi + a) = h;
    *reinterpret_cast<uint2*>(lo + a) = l;
}

// ---------------- K1: persistent-W split-bf16 HMMA (R12, unchanged) ----------
#define SM_FHI 0
#define SM_FLO 16384
#define SM_WHI 32768
#define SM_WLO 65536
#define K1_SMEM 98304
#define NTILE_STRIDE 32

__global__ void __launch_bounds__(256, 2)
k1_gemm(const float* __restrict__ F, const float* __restrict__ Wg, int N)
{
    extern __shared__ char smem[];
    const uint32_t sb = smem_u32(smem);
    const int tid  = threadIdx.x;
    const int lane = tid & 31;
    const int warp = tid >> 5;
    const int rg   = warp & 1;
    const int cg   = warp >> 1;
    const int m    = blockIdx.y;
    const int ntiles = (N + 63) / 64;
    const float4* Fg4 = reinterpret_cast<const float4*>(F);
    const float4* Wg4 = reinterpret_cast<const float4*>(Wg);

    int lrow[8], lq[8];
    #pragma unroll
    for (int it = 0; it < 8; ++it) {
        int s = tid + it * 256;
        lrow[it] = s >> 5; lq[it] = s & 31;
    }

    float4 fraw[8];
    {
        const int n0 = blockIdx.x * 64;
        #pragma unroll
        for (int it = 0; it < 8; ++it) {
            int n = n0 + lrow[it];
            fraw[it] = make_float4(0.f, 0.f, 0.f, 0.f);
            if (n < N) fraw[it] = Fg4[((size_t)n * MM + m) * 32 + lq[it]];
        }
    }

    #pragma unroll
    for (int it = 0; it < 16; ++it) {
        int s = tid + it * 256;
        int row = s >> 5, q = s & 31;
        st_split_g(smem + SM_WHI, smem + SM_WLO, bswz(row, q),
                   Wg4[(size_t)m * 4096 + s]);
    }
    __syncthreads();

    const int a_row0 = 32 * rg + (lane & 15);
    const int a_ch   = lane >> 4;
    const int b_rlo  = (lane & 7) + ((lane >> 4) << 3);
    const int b_ch   = (lane >> 3) & 1;

    for (int t = blockIdx.x; t < ntiles; t += NTILE_STRIDE) {
        const int n0 = t * 64;

        #pragma unroll
        for (int it = 0; it < 8; ++it)
            st_split_g(smem + SM_FHI, smem + SM_FLO, bswz(lrow[it], lq[it]), fraw[it]);
        __syncthreads();

        const int tn = t + NTILE_STRIDE;
        if (tn < ntiles) {
            const int nn0 = tn * 64;
            #pragma unroll
            for (int it = 0; it < 8; ++it) {
                int n = nn0 + lrow[it];
                fraw[it] = make_float4(0.f, 0.f, 0.f, 0.f);
                if (n < N) fraw[it] = Fg4[((size_t)n * MM + m) * 32 + lq[it]];
            }
        }

        float acc[2][4][4];
        #pragma unroll
        for (int rt = 0; rt < 2; ++rt)
            #pragma unroll
            for (int q = 0; q < 4; ++q)
                #pragma unroll
                for (int c = 0; c < 4; ++c) acc[rt][q][c] = 0.f;

        #pragma unroll
        for (int kk = 0; kk < 8; ++kk) {
            uint32_t ah[2][4], al[2][4];
            #pragma unroll
            for (int rt = 0; rt < 2; ++rt) {
                LDSM_X4(ah[rt][0], ah[rt][1], ah[rt][2], ah[rt][3],
                        lmaddr(sb + SM_FHI, a_row0 + 16 * rt, 2 * kk + a_ch));
                LDSM_X4(al[rt][0], al[rt][1], al[rt][2], al[rt][3],
                        lmaddr(sb + SM_FLO, a_row0 + 16 * rt, 2 * kk + a_ch));
            }
            uint32_t bh[2][4], bl[2][4];
            #pragma unroll
            for (int ct = 0; ct < 2; ++ct) {
                const int brow = 32 * cg + 16 * ct + b_rlo;
                LDSM_X4(bh[ct][0], bh[ct][1], bh[ct][2], bh[ct][3],
                        lmaddr(sb + SM_WHI, brow, 2 * kk + b_ch));
                LDSM_X4(bl[ct][0], bl[ct][1], bl[ct][2], bl[ct][3],
                        lmaddr(sb + SM_WLO, brow, 2 * kk + b_ch));
            }
            #pragma unroll
            for (int rt = 0; rt < 2; ++rt) {
                #pragma unroll
                for (int q = 0; q < 4; ++q) {
                    const int ct = q >> 1, h = (q & 1) * 2;
                    HMMA(acc[rt][q][0], acc[rt][q][1], acc[rt][q][2], acc[rt][q][3],
                         ah[rt][0], ah[rt][1], ah[rt][2], ah[rt][3],
                         bh[ct][h], bh[ct][h + 1]);
                    HMMA(acc[rt][q][0], acc[rt][q][1], acc[rt][q][2], acc[rt][q][3],
                         ah[rt][0], ah[rt][1], ah[rt][2], ah[rt][3],
                         bl[ct][h], bl[ct][h + 1]);
                    HMMA(acc[rt][q][0], acc[rt][q][1], acc[rt][q][2], acc[rt][q][3],
                         al[rt][0], al[rt][1], al[rt][2], al[rt][3],
                         bh[ct][h], bh[ct][h + 1]);
                }
            }
        }

        #pragma unroll
        for (int rt = 0; rt < 2; ++rt) {
            const int r0 = n0 + 32 * rg + 16 * rt + (lane >> 2);
            const int cb = 32 * cg + (lane & 3) * 2;
            #pragma unroll
            for (int q = 0; q < 4; ++q) {
                const int col = cb + 8 * q;
                if (r0 < N) {
                    __half2 v = __floats2half2_rn(fmaxf(acc[rt][q][0], 0.f),
                                                  fmaxf(acc[rt][q][1], 0.f));
                    *reinterpret_cast<__half2*>(g_h + ((size_t)r0 * MM + m) * DD + col) = v;
                }
                if (r0 + 8 < N) {
                    __half2 v = __floats2half2_rn(fmaxf(acc[rt][q][2], 0.f),
                                                  fmaxf(acc[rt][q][3], 0.f));
                    *reinterpret_cast<__half2*>(g_h + ((size_t)(r0 + 8) * MM + m) * DD + col) = v;
                }
            }
        }
        __syncthreads();
    }
}

// ---------------- K2: tensor-core Gram phase 2 -------------------------------
// 1 warp = 1 example at a time (4 per warp); G = g g^T via fp16 HMMA (exact
// given fp16 g); s_jk = G_jj + G_kk - 2 G_jk; pairs computed lane-parallel.
#define K2_EXW 4
#define K2_WSTRIDE 5376      // stage 4096 | G 1024 | E 144 (+pad)
#define K2_SMEM (8 * K2_WSTRIDE)

__device__ __forceinline__ constexpr int pidx(int j, int k) {
    return j * 8 - j * (j - 1) / 2 + (k - j - 1);
}

__global__ void __launch_bounds__(256)
k2_phase2(const float* __restrict__ F, float* __restrict__ out, int N)
{
    __shared__ char smem2[K2_SMEM];
    const int lane = threadIdx.x & 31;
    const int warp = threadIdx.x >> 5;
    char*  stage = smem2 + warp * K2_WSTRIDE;
    float* G = reinterpret_cast<float*>(stage + 4096);
    float* E = reinterpret_cast<float*>(stage + 5120);
    const uint32_t stage_u = smem_u32(stage);
    const float4* Fg4 = reinterpret_cast<const float4*>(F);
    float4* out4 = reinterpret_cast<float4*>(out);

    const int a_row = lane & 15;
    const int a_ch  = lane >> 4;
    const int b_rlo = (lane & 7) + ((lane >> 4) << 3);
    const int b_ch  = (lane >> 3) & 1;
    const int pj1 = PJ_d[lane], pk1 = PK_d[lane];   // pair lane
    const int pj2 = (lane < 4) ? PJ_d[lane + 32] : 0;
    const int pk2 = (lane < 4) ? PK_d[lane + 32] : 1;

    for (int e = 0; e < K2_EXW; ++e) {
        const int n = blockIdx.x * (8 * K2_EXW) + warp * K2_EXW + e;
        if (n >= N) break;   // warp-uniform

        // 1) stage g[n] (9 x 128 fp16) into swizzled smem (144 x 16B)
        const uint4* gsrc = reinterpret_cast<const uint4*>(g_h + (size_t)n * MM * DD);
        #pragma unroll
        for (int i0 = 0; i0 < 5; ++i0) {
            int i = lane + i0 * 32;
            if (i < 144) {
                int row = i >> 4, c = i & 15;
                int cs_ = (c & 8) | ((c & 7) ^ (row & 7));
                *reinterpret_cast<uint4*>(stage + row * 256 + cs_ * 16) = gsrc[i];
            }
        }
        __syncwarp();

        // 2) Gram: 8 kk x (A ldsm + B ldsm + 2 HMMA f16)
        float ac0[4] = {0.f, 0.f, 0.f, 0.f};
        float ac1[4] = {0.f, 0.f, 0.f, 0.f};
        #pragma unroll
        for (int kk = 0; kk < 8; ++kk) {
            uint32_t a0, a1, a2, a3, b0, b1, b2, b3;
            LDSM_X4(a0, a1, a2, a3, lmaddr(stage_u, a_row, 2 * kk + a_ch));
            LDSM_X4(b0, b1, b2, b3, lmaddr(stage_u, b_rlo, 2 * kk + b_ch));
            HMMA16(ac0[0], ac0[1], ac0[2], ac0[3], a0, a1, a2, a3, b0, b1);
            HMMA16(ac1[0], ac1[1], ac1[2], ac1[3], a0, a1, a2, a3, b2, b3);
        }

        // 3) write G (16x16 fp32): rows r,r+8 ; cols 2c,2c+1 (+8 for tile 1)
        {
            const int r = lane >> 2, c2 = (lane & 3) * 2;
            G[r * 16 + c2]            = ac0[0];
            G[r * 16 + c2 + 1]        = ac0[1];
            G[(r + 8) * 16 + c2]      = ac0[2];
            G[(r + 8) * 16 + c2 + 1]  = ac0[3];
            G[r * 16 + 8 + c2]        = ac1[0];
            G[r * 16 + 8 + c2 + 1]    = ac1[1];
            G[(r + 8) * 16 + 8 + c2]  = ac1[2];
            G[(r + 8) * 16 + 8 + c2 + 1] = ac1[3];
        }
        __syncwarp();

        // 4) pairs lane-parallel: s = Gjj + Gkk - 2 Gjk; e = tanh(sqrt(s))
        {
            float s = G[pj1 * 16 + pj1] + G[pk1 * 16 + pk1] - 2.f * G[pj1 * 16 + pk1];
            float x = (s > 0.f) ? s * __frsqrt_rn(s) : 0.f;
            E[lane] = 1.f - __fdividef(2.f, __expf(2.f * x) + 1.f);
            if (lane < 4) {
                float s2 = G[pj2 * 16 + pj2] + G[pk2 * 16 + pk2] - 2.f * G[pj2 * 16 + pk2];
                float x2 = (s2 > 0.f) ? s2 * __frsqrt_rn(s2) : 0.f;
                E[lane + 32] = 1.f - __fdividef(2.f, __expf(2.f * x2) + 1.f);
            }
        }
        __syncwarp();

        // 5) cs[k] (broadcast LDS, compile-time indices), u, fsum, out
        float cs_[MM];
        #pragma unroll
        for (int k = 0; k < MM; ++k) {
            float a = 0.f;
            #pragma unroll
            for (int j = 0; j < MM; ++j) {
                if (j == k) continue;
                a += E[(j < k) ? pidx(j, k) : pidx(k, j)];
            }
            cs_[k] = a;
        }

        // g for this lane's 4 dims from staging (fp16, swizzled)
        float4 u = make_float4(0.f, 0.f, 0.f, 0.f);
        #pragma unroll
        for (int m = 0; m < MM; ++m) {
            int c = lane >> 1;
            int cs2 = (c & 8) | ((c & 7) ^ (m & 7));
            uint2 raw = *reinterpret_cast<const uint2*>(
                stage + m * 256 + cs2 * 16 + (lane & 1) * 8);
            float2 f0 = __half22float2(*reinterpret_cast<const __half2*>(&raw.x));
            float2 f1 = __half22float2(*reinterpret_cast<const __half2*>(&raw.y));
            u.x = fmaf(cs_[m], f0.x, u.x);
            u.y = fmaf(cs_[m], f0.y, u.y);
            u.z = fmaf(cs_[m], f1.x, u.z);
            u.w = fmaf(cs_[m], f1.y, u.w);
        }

        float4 fs = Fg4[((size_t)n * MM) * 32 + lane];
        #pragma unroll
        for (int m = 1; m < MM; ++m) {
            float4 v = Fg4[((size_t)n * MM + m) * 32 + lane];
            fs.x += v.x; fs.y += v.y; fs.z += v.z; fs.w += v.w;
        }

        float4 o;
        o.x = 0.5f * (fs.x + u.x);
        o.y = 0.5f * (fs.y + u.y);
        o.z = 0.5f * (fs.z + u.z);
        o.w = 0.5f * (fs.w + u.w);
        out4[(size_t)n * 32 + lane] = o;
        __syncwarp();   // E/G/stage consumed before next example overwrites
    }
}

// ----------------------------------------------------------------------------
extern "C" void kernel_launch(void* const* d_in, const int* in_sizes, int n_in,
                              void* d_out, int out_size) {
    const float* F = (const float*)d_in[0];   // [N,9,128] fp32
    const float* W = (const float*)d_in[1];   // [9,128,128] fp32
    float* out = (float*)d_out;               // [N,128] fp32
    const int N = in_sizes[0] / (MM * DD);

    cudaFuncSetAttribute(k1_gemm, cudaFuncAttributeMaxDynamicSharedMemorySize, K1_SMEM);

    dim3 g1(NTILE_STRIDE, MM);
    k1_gemm<<<g1, 256, K1_SMEM>>>(F, W, N);
    k2_phase2<<<(N + 31) / 32, 256>>>(F, out, N);
}

// round 15
// speedup vs baseline: 1.8654x; 1.4249x over previous
#include <cuda_runtime.h>
#include <cuda_bf16.h>
#include <cuda_fp16.h>
#include <cstdint>

#define MM 9
#define DD 128
#define NMAX 8192

// ---------------- global scratch (static, no dynamic alloc) ----------------
static __device__ __align__(128) __half g_h[NMAX * MM * DD];   // 18.9 MB fp16

// pair index tables: pair p -> (j, k), j < k
static __device__ const int PJ_d[36] =
    {0,0,0,0,0,0,0,0, 1,1,1,1,1,1,1, 2,2,2,2,2,2, 3,3,3,3,3, 4,4,4,4, 5,5,5, 6,6, 7};
static __device__ const int PK_d[36] =
    {1,2,3,4,5,6,7,8, 2,3,4,5,6,7,8, 3,4,5,6,7,8, 4,5,6,7,8, 5,6,7,8, 6,7,8, 7,8, 8};

// ---------------- helpers ---------------------------------------------------
__device__ __forceinline__ uint32_t bswz(int row, int q) {
    int c = q >> 1;
    int cs = (c & 8) | ((c & 7) ^ (row & 7));
    return (uint32_t)(row * 256 + cs * 16 + (q & 1) * 8);
}
__device__ __forceinline__ uint32_t lmaddr(uint32_t base, int row, int chunk) {
    int cs = (chunk & 8) | ((chunk & 7) ^ (row & 7));
    return base + (uint32_t)(row * 256 + cs * 16);
}
__device__ __forceinline__ uint32_t smem_u32(const void* p) {
    uint32_t a;
    asm("{ .reg .u64 t; cvta.to.shared.u64 t, %1; cvt.u32.u64 %0, t; }" : "=r"(a) : "l"(p));
    return a;
}
#define LDSM_X4(r0, r1, r2, r3, a) \
    asm volatile("ldmatrix.sync.aligned.m8n8.x4.shared.b16 {%0,%1,%2,%3}, [%4];" \
                 : "=r"(r0), "=r"(r1), "=r"(r2), "=r"(r3) : "r"(a))
#define HMMA16(d0, d1, d2, d3, a0, a1, a2, a3, b0, b1) \
    asm volatile("mma.sync.aligned.m16n8k16.row.col.f32.f16.f16.f32 " \
                 "{%0,%1,%2,%3}, {%4,%5,%6,%7}, {%8,%9}, {%0,%1,%2,%3};" \
                 : "+f"(d0), "+f"(d1), "+f"(d2), "+f"(d3) \
                 : "r"(a0), "r"(a1), "r"(a2), "r"(a3), "r"(b0), "r"(b1))

// convert one float4 -> 4 fp16, store 8B at swizzled address
__device__ __forceinline__ void st_h4(char* base, uint32_t a, float4 v) {
    __half2 h0 = __floats2half2_rn(v.x, v.y);
    __half2 h1 = __floats2half2_rn(v.z, v.w);
    uint2 h;
    h.x = *reinterpret_cast<uint32_t*>(&h0);
    h.y = *reinterpret_cast<uint32_t*>(&h1);
    *reinterpret_cast<uint2*>(base + a) = h;
}

__device__ __forceinline__ constexpr int pidx(int j, int k) {
    return j * 8 - j * (j - 1) / 2 + (k - j - 1);
}

// ---------------- K1: persistent-W single-fp16 HMMA --------------------------
// grid (32, 9), 256 thr; smem: W 32K | f 16K = 48K
#define SM_WH 0
#define SM_FH 32768
#define K1_SMEM 49152
#define NTILE_STRIDE 32

__global__ void __launch_bounds__(256, 2)
k1_gemm(const float* __restrict__ F, const float* __restrict__ Wg, int N)
{
    extern __shared__ char smem[];
    const uint32_t sb = smem_u32(smem);
    const int tid  = threadIdx.x;
    const int lane = tid & 31;
    const int warp = tid >> 5;          // 0..7
    const int rg   = warp & 1;          // rows [32rg, 32rg+32)
    const int cg   = warp >> 1;         // cols [32cg, 32cg+32)
    const int m    = blockIdx.y;
    const int ntiles = (N + 63) / 64;
    const float4* Fg4 = reinterpret_cast<const float4*>(F);
    const float4* Wg4 = reinterpret_cast<const float4*>(Wg);

    int lrow[8], lq[8];
    #pragma unroll
    for (int it = 0; it < 8; ++it) {
        int s = tid + it * 256;
        lrow[it] = s >> 5; lq[it] = s & 31;
    }

    // prefetch f for first tile
    float4 fraw[8];
    {
        const int n0 = blockIdx.x * 64;
        #pragma unroll
        for (int it = 0; it < 8; ++it) {
            int n = n0 + lrow[it];
            fraw[it] = make_float4(0.f, 0.f, 0.f, 0.f);
            if (n < N) fraw[it] = Fg4[((size_t)n * MM + m) * 32 + lq[it]];
        }
    }

    // convert W_m (fp32, L2-resident) into fp16 smem, ONCE per CTA
    #pragma unroll
    for (int it = 0; it < 16; ++it) {
        int s = tid + it * 256;
        int row = s >> 5, q = s & 31;
        st_h4(smem + SM_WH, bswz(row, q), Wg4[(size_t)m * 4096 + s]);
    }
    __syncthreads();

    const int a_row0 = 32 * rg + (lane & 15);
    const int a_ch   = lane >> 4;
    const int b_rlo  = (lane & 7) + ((lane >> 4) << 3);
    const int b_ch   = (lane >> 3) & 1;

    for (int t = blockIdx.x; t < ntiles; t += NTILE_STRIDE) {
        const int n0 = t * 64;

        #pragma unroll
        for (int it = 0; it < 8; ++it)
            st_h4(smem + SM_FH, bswz(lrow[it], lq[it]), fraw[it]);
        __syncthreads();

        const int tn = t + NTILE_STRIDE;
        if (tn < ntiles) {
            const int nn0 = tn * 64;
            #pragma unroll
            for (int it = 0; it < 8; ++it) {
                int n = nn0 + lrow[it];
                fraw[it] = make_float4(0.f, 0.f, 0.f, 0.f);
                if (n < N) fraw[it] = Fg4[((size_t)n * MM + m) * 32 + lq[it]];
            }
        }

        float acc[2][4][4];
        #pragma unroll
        for (int rt = 0; rt < 2; ++rt)
            #pragma unroll
            for (int q = 0; q < 4; ++q)
                #pragma unroll
                for (int c = 0; c < 4; ++c) acc[rt][q][c] = 0.f;

        #pragma unroll
        for (int kk = 0; kk < 8; ++kk) {
            uint32_t ah[2][4], bh[2][4];
            #pragma unroll
            for (int rt = 0; rt < 2; ++rt)
                LDSM_X4(ah[rt][0], ah[rt][1], ah[rt][2], ah[rt][3],
                        lmaddr(sb + SM_FH, a_row0 + 16 * rt, 2 * kk + a_ch));
            #pragma unroll
            for (int ct = 0; ct < 2; ++ct) {
                const int brow = 32 * cg + 16 * ct + b_rlo;
                LDSM_X4(bh[ct][0], bh[ct][1], bh[ct][2], bh[ct][3],
                        lmaddr(sb + SM_WH, brow, 2 * kk + b_ch));
            }
            #pragma unroll
            for (int rt = 0; rt < 2; ++rt) {
                #pragma unroll
                for (int q = 0; q < 4; ++q) {
                    const int ct = q >> 1, h = (q & 1) * 2;
                    HMMA16(acc[rt][q][0], acc[rt][q][1], acc[rt][q][2], acc[rt][q][3],
                           ah[rt][0], ah[rt][1], ah[rt][2], ah[rt][3],
                           bh[ct][h], bh[ct][h + 1]);
                }
            }
        }

        // relu + store g as fp16
        #pragma unroll
        for (int rt = 0; rt < 2; ++rt) {
            const int r0 = n0 + 32 * rg + 16 * rt + (lane >> 2);
            const int cb = 32 * cg + (lane & 3) * 2;
            #pragma unroll
            for (int q = 0; q < 4; ++q) {
                const int col = cb + 8 * q;
                if (r0 < N) {
                    __half2 v = __floats2half2_rn(fmaxf(acc[rt][q][0], 0.f),
                                                  fmaxf(acc[rt][q][1], 0.f));
                    *reinterpret_cast<__half2*>(g_h + ((size_t)r0 * MM + m) * DD + col) = v;
                }
                if (r0 + 8 < N) {
                    __half2 v = __floats2half2_rn(fmaxf(acc[rt][q][2], 0.f),
                                                  fmaxf(acc[rt][q][3], 0.f));
                    *reinterpret_cast<__half2*>(g_h + ((size_t)(r0 + 8) * MM + m) * DD + col) = v;
                }
            }
        }
        __syncthreads();
    }
}

// ---------------- K2: tensor-core Gram phase 2, 1 example per warp -----------
#define K2_WSTRIDE 5376      // stage 4096 | G 1024 | E 144 (+pad)
#define K2_SMEM (8 * K2_WSTRIDE)

__global__ void __launch_bounds__(256)
k2_phase2(const float* __restrict__ F, float* __restrict__ out, int N)
{
    __shared__ char smem2[K2_SMEM];
    const int lane = threadIdx.x & 31;
    const int warp = threadIdx.x >> 5;
    char*  stage = smem2 + warp * K2_WSTRIDE;
    float* G = reinterpret_cast<float*>(stage + 4096);
    float* E = reinterpret_cast<float*>(stage + 5120);
    const uint32_t stage_u = smem_u32(stage);
    const float4* Fg4 = reinterpret_cast<const float4*>(F);
    float4* out4 = reinterpret_cast<float4*>(out);

    const int n = blockIdx.x * 8 + warp;
    if (n >= N) return;      // warp-uniform

    const int a_row = lane & 15;
    const int a_ch  = lane >> 4;
    const int b_rlo = (lane & 7) + ((lane >> 4) << 3);
    const int b_ch  = (lane >> 3) & 1;
    const int pj1 = PJ_d[lane], pk1 = PK_d[lane];
    const int pj2 = (lane < 4) ? PJ_d[lane + 32] : 0;
    const int pk2 = (lane < 4) ? PK_d[lane + 32] : 1;

    // 0) fsum LDGs issued first: overlap staging + Gram below
    float4 fs = Fg4[((size_t)n * MM) * 32 + lane];
    #pragma unroll
    for (int m = 1; m < MM; ++m) {
        float4 v = Fg4[((size_t)n * MM + m) * 32 + lane];
        fs.x += v.x; fs.y += v.y; fs.z += v.z; fs.w += v.w;
    }

    // 1) stage g[n] (9 x 128 fp16) into swizzled smem (144 x 16B)
    const uint4* gsrc = reinterpret_cast<const uint4*>(g_h + (size_t)n * MM * DD);
    #pragma unroll
    for (int i0 = 0; i0 < 5; ++i0) {
        int i = lane + i0 * 32;
        if (i < 144) {
            int row = i >> 4, c = i & 15;
            int cs_ = (c & 8) | ((c & 7) ^ (row & 7));
            *reinterpret_cast<uint4*>(stage + row * 256 + cs_ * 16) = gsrc[i];
        }
    }
    __syncwarp();

    // 2) Gram: 8 kk x (A ldsm + B ldsm + 2 HMMA f16)
    float ac0[4] = {0.f, 0.f, 0.f, 0.f};
    float ac1[4] = {0.f, 0.f, 0.f, 0.f};
    #pragma unroll
    for (int kk = 0; kk < 8; ++kk) {
        uint32_t a0, a1, a2, a3, b0, b1, b2, b3;
        LDSM_X4(a0, a1, a2, a3, lmaddr(stage_u, a_row, 2 * kk + a_ch));
        LDSM_X4(b0, b1, b2, b3, lmaddr(stage_u, b_rlo, 2 * kk + b_ch));
        HMMA16(ac0[0], ac0[1], ac0[2], ac0[3], a0, a1, a2, a3, b0, b1);
        HMMA16(ac1[0], ac1[1], ac1[2], ac1[3], a0, a1, a2, a3, b2, b3);
    }

    // 3) write G (16x16 fp32)
    {
        const int r = lane >> 2, c2 = (lane & 3) * 2;
        G[r * 16 + c2]               = ac0[0];
        G[r * 16 + c2 + 1]           = ac0[1];
        G[(r + 8) * 16 + c2]         = ac0[2];
        G[(r + 8) * 16 + c2 + 1]     = ac0[3];
        G[r * 16 + 8 + c2]           = ac1[0];
        G[r * 16 + 8 + c2 + 1]       = ac1[1];
        G[(r + 8) * 16 + 8 + c2]     = ac1[2];
        G[(r + 8) * 16 + 8 + c2 + 1] = ac1[3];
    }
    __syncwarp();

    // 4) pairs lane-parallel: s = Gjj + Gkk - 2 Gjk; e = tanh(sqrt(s))
    {
        float s = G[pj1 * 16 + pj1] + G[pk1 * 16 + pk1] - 2.f * G[pj1 * 16 + pk1];
        float x = (s > 0.f) ? s * __frsqrt_rn(s) : 0.f;
        E[lane] = 1.f - __fdividef(2.f, __expf(2.f * x) + 1.f);
        if (lane < 4) {
            float s2 = G[pj2 * 16 + pj2] + G[pk2 * 16 + pk2] - 2.f * G[pj2 * 16 + pk2];
            float x2 = (s2 > 0.f) ? s2 * __frsqrt_rn(s2) : 0.f;
            E[lane + 32] = 1.f - __fdividef(2.f, __expf(2.f * x2) + 1.f);
        }
    }
    __syncwarp();

    // 5) cs[k], u, output
    float cs_[MM];
    #pragma unroll
    for (int k = 0; k < MM; ++k) {
        float a = 0.f;
        #pragma unroll
        for (int j = 0; j < MM; ++j) {
            if (j == k) continue;
            a += E[(j < k) ? pidx(j, k) : pidx(k, j)];
        }
        cs_[k] = a;
    }

    float4 u = make_float4(0.f, 0.f, 0.f, 0.f);
    #pragma unroll
    for (int m = 0; m < MM; ++m) {
        int c = lane >> 1;
        int cs2 = (c & 8) | ((c & 7) ^ (m & 7));
        uint2 raw = *reinterpret_cast<const uint2*>(
            stage + m * 256 + cs2 * 16 + (lane & 1) * 8);
        float2 f0 = __half22float2(*reinterpret_cast<const __half2*>(&raw.x));
        float2 f1 = __half22float2(*reinterpret_cast<const __half2*>(&raw.y));
        u.x = fmaf(cs_[m], f0.x, u.x);
        u.y = fmaf(cs_[m], f0.y, u.y);
        u.z = fmaf(cs_[m], f1.x, u.z);
        u.w = fmaf(cs_[m], f1.y, u.w);
    }

    float4 o;
    o.x = 0.5f * (fs.x + u.x);
    o.y = 0.5f * (fs.y + u.y);
    o.z = 0.5f * (fs.z + u.z);
    o.w = 0.5f * (fs.w + u.w);
    out4[(size_t)n * 32 + lane] = o;
}

// ----------------------------------------------------------------------------
extern "C" void kernel_launch(void* const* d_in, const int* in_sizes, int n_in,
                              void* d_out, int out_size) {
    const float* F = (const float*)d_in[0];   // [N,9,128] fp32
    const float* W = (const float*)d_in[1];   // [9,128,128] fp32
    float* out = (float*)d_out;               // [N,128] fp32
    const int N = in_sizes[0] / (MM * DD);

    cudaFuncSetAttribute(k1_gemm, cudaFuncAttributeMaxDynamicSharedMemorySize, K1_SMEM);

    dim3 g1(NTILE_STRIDE, MM);
    k1_gemm<<<g1, 256, K1_SMEM>>>(F, W, N);
    k2_phase2<<<(N + 7) / 8, 256>>>(F, out, N);
}